// round 13
// baseline (speedup 1.0000x reference)
#include <cuda_runtime.h>
#include <cstdint>

// Problem shape (fixed by the dataset)
#define B_BATCH 4
#define E_EDGES 320000
#define N_NODES 10000
#define F_FEAT  64
#define E_TOTAL (B_BATCH * E_EDGES)                // 1,280,000

#define THREADS       128
#define CHUNK         128                          // edges per chunk (1 per thread)
#define NSTAGES       3
#define TOTAL_CHUNKS  (E_TOTAL / CHUNK)            // 10000 (exact)
#define CHUNKS_PER_B  (E_EDGES / CHUNK)            // 2500 (exact, no straddle)
#define NCTAS         296                          // 2 CTAs per SM

#define MSG_BYTES     (CHUNK * F_FEAT * 4)         // 32768
#define IDX_BYTES     (CHUNK * 4)                  // 512
#define STAGE_BYTES   (MSG_BYTES + IDX_BYTES)      // 33280
#define SMEM_DATA     (NSTAGES * STAGE_BYTES)      // 99840
#define SMEM_BYTES    (SMEM_DATA + NSTAGES * 8)    // + full barriers

__device__ __forceinline__ void mbar_init(uint32_t a, uint32_t cnt) {
    asm volatile("mbarrier.init.shared.b64 [%0], %1;" :: "r"(a), "r"(cnt) : "memory");
}
__device__ __forceinline__ void mbar_expect_tx(uint32_t a, uint32_t bytes) {
    asm volatile("mbarrier.arrive.expect_tx.shared.b64 _, [%0], %1;"
                 :: "r"(a), "r"(bytes) : "memory");
}
__device__ __forceinline__ void mbar_wait(uint32_t a, uint32_t parity) {
    asm volatile(
        "{\n\t.reg .pred P;\n\t"
        "W_%=:\n\t"
        "mbarrier.try_wait.parity.acquire.cta.shared::cta.b64 P, [%0], %1, 0x989680;\n\t"
        "@P bra.uni D_%=;\n\t"
        "bra.uni W_%=;\n\t"
        "D_%=:\n\t}"
        :: "r"(a), "r"(parity) : "memory");
}
__device__ __forceinline__ void bulk_g2s(uint32_t dst, const void* src,
                                         uint32_t bytes, uint32_t mbar) {
    asm volatile(
        "cp.async.bulk.shared::cta.global.mbarrier::complete_tx::bytes [%0], [%1], %2, [%3];"
        :: "r"(dst), "l"(src), "r"(bytes), "r"(mbar) : "memory");
}
// 256B f32-add RMW executed by the TMA engine (async proxy; bypasses L1tex).
__device__ __forceinline__ void bulk_reduce_add(float* gdst, uint32_t ssrc, uint32_t bytes) {
    asm volatile(
        "cp.reduce.async.bulk.global.shared::cta.bulk_group.add.f32 [%0], [%1], %2;"
        :: "l"(gdst), "r"(ssrc), "r"(bytes) : "memory");
}
#define BULK_COMMIT() asm volatile("cp.async.bulk.commit_group;" ::: "memory")
#define BULK_WAIT0()  asm volatile("cp.async.bulk.wait_group 0;" ::: "memory")

// All-TMA scatter-add: msg+idx staged in via cp.async.bulk, each edge flushed
// out as ONE 256B cp.reduce.async.bulk. The SM's L1tex pipeline (the suspected
// ~70us wavefront bottleneck of the RED-based kernels) carries only tiny LDS.
__global__ __launch_bounds__(THREADS, 2) void scatter_tmared_kernel(
    const float4* __restrict__ msg,   // [B*E, 16] float4 (batches contiguous)
    const int*    __restrict__ idx,   // [B*E]
    float*        __restrict__ out)   // [B, N, 64]
{
    extern __shared__ __align__(256) char smem[];
    const uint32_t sb  = (uint32_t)__cvta_generic_to_shared(smem);
    const uint32_t mbb = sb + SMEM_DATA;
    const int tid = threadIdx.x;

    if (tid == 0) {
#pragma unroll
        for (int s = 0; s < NSTAGES; ++s) mbar_init(mbb + s * 8, 1);
        asm volatile("fence.proxy.async.shared::cta;" ::: "memory");
    }
    __syncthreads();

    auto issue = [&](int c, int st) {
        const uint32_t full = mbb + st * 8;
        const uint32_t sp   = sb + st * STAGE_BYTES;
        mbar_expect_tx(full, STAGE_BYTES);
        bulk_g2s(sp,             msg + (long long)c * (CHUNK * 16), MSG_BYTES, full);
        bulk_g2s(sp + MSG_BYTES, idx + (long long)c * CHUNK,        IDX_BYTES, full);
    };

    // Prologue: leader fills stages 0 and 1.
    if (tid == 0) {
#pragma unroll
        for (int p = 0; p < NSTAGES - 1; ++p) {
            const int c = blockIdx.x + p * NCTAS;
            if (c < TOTAL_CHUNKS) issue(c, p);
        }
    }

    for (int k = 0;; ++k) {
        const int c = blockIdx.x + k * NCTAS;
        if (c >= TOTAL_CHUNKS) break;
        const int st = k % NSTAGES;

        // Recycle stage (k+2)%NSTAGES: it was consumed at iter k-1; wait for
        // MY reduce group from k-1 to finish reading it, then sync the CTA so
        // the leader may overwrite it.
        if (k > 0) BULK_WAIT0();
        __syncthreads();
        if (tid == 0) {
            const int cf = blockIdx.x + (k + NSTAGES - 1) * NCTAS;
            if (cf < TOTAL_CHUNKS) issue(cf, (k + NSTAGES - 1) % NSTAGES);
        }

        // Consume stage st once its TMA load lands.
        mbar_wait(mbb + st * 8, (uint32_t)((k / NSTAGES) & 1));

        const int  b    = c / CHUNKS_PER_B;
        const int* sidx = reinterpret_cast<const int*>(smem + st * STAGE_BYTES + MSG_BYTES);
        const int  node = sidx[tid];              // one edge per thread
        float* dst = out + ((long long)b * N_NODES + node) * F_FEAT;
        bulk_reduce_add(dst, sb + st * STAGE_BYTES + tid * 256, 256);
        BULK_COMMIT();
    }

    BULK_WAIT0();   // drain outstanding reductions before exit
}

extern "C" void kernel_launch(void* const* d_in, const int* in_sizes, int n_in,
                              void* d_out, int out_size) {
    const float4* msg = (const float4*)d_in[0];   // msg_vectors [B,E,F] f32
    const int*    idx = (const int*)d_in[1];      // start_indices [B,E] i32
    // d_in[2] = h_v, unused by the reference computation
    float* out = (float*)d_out;                   // [B,N,F] f32

    static bool attr_set = false;
    if (!attr_set) {
        cudaFuncSetAttribute(scatter_tmared_kernel,
                             cudaFuncAttributeMaxDynamicSharedMemorySize, SMEM_BYTES);
        attr_set = true;
    }

    // 1) zero the output (harness poisons it with 0xAA)
    cudaMemsetAsync(out, 0, (size_t)out_size * sizeof(float), 0);

    // 2) all-TMA pipelined scatter-reduce (2 CTAs/SM)
    scatter_tmared_kernel<<<NCTAS, THREADS, SMEM_BYTES>>>(msg, idx, out);
}

// round 14
// speedup vs baseline: 1.0784x; 1.0784x over previous
#include <cuda_runtime.h>
#include <cstdint>

// Problem shape (fixed by the dataset)
#define B_BATCH 4
#define E_EDGES 320000
#define N_NODES 10000
#define F_FEAT  64
#define E_TOTAL (B_BATCH * E_EDGES)                // 1,280,000

#define THREADS       128
#define CHUNK         128                          // edges per chunk (1 per thread)
#define NSTAGES       5
#define PROLOGUE      2                            // stages filled up front
#define TOTAL_CHUNKS  (E_TOTAL / CHUNK)            // 10000 (exact)
#define CHUNKS_PER_B  (E_EDGES / CHUNK)            // 2500 (exact, no straddle)
#define NCTAS         148                          // 1 CTA per SM

#define MSG_BYTES     (CHUNK * F_FEAT * 4)         // 32768
#define IDX_BYTES     (CHUNK * 4)                  // 512
#define STAGE_BYTES   (MSG_BYTES + IDX_BYTES)      // 33280
#define SMEM_DATA     (NSTAGES * STAGE_BYTES)      // 166400
#define SMEM_BYTES    (SMEM_DATA + NSTAGES * 8)    // + full barriers

__device__ __forceinline__ void mbar_init(uint32_t a, uint32_t cnt) {
    asm volatile("mbarrier.init.shared.b64 [%0], %1;" :: "r"(a), "r"(cnt) : "memory");
}
__device__ __forceinline__ void mbar_expect_tx(uint32_t a, uint32_t bytes) {
    asm volatile("mbarrier.arrive.expect_tx.shared.b64 _, [%0], %1;"
                 :: "r"(a), "r"(bytes) : "memory");
}
__device__ __forceinline__ void mbar_wait(uint32_t a, uint32_t parity) {
    asm volatile(
        "{\n\t.reg .pred P;\n\t"
        "W_%=:\n\t"
        "mbarrier.try_wait.parity.acquire.cta.shared::cta.b64 P, [%0], %1, 0x989680;\n\t"
        "@P bra.uni D_%=;\n\t"
        "bra.uni W_%=;\n\t"
        "D_%=:\n\t}"
        :: "r"(a), "r"(parity) : "memory");
}
__device__ __forceinline__ void bulk_g2s(uint32_t dst, const void* src,
                                         uint32_t bytes, uint32_t mbar) {
    asm volatile(
        "cp.async.bulk.shared::cta.global.mbarrier::complete_tx::bytes [%0], [%1], %2, [%3];"
        :: "r"(dst), "l"(src), "r"(bytes), "r"(mbar) : "memory");
}
// 256B f32-add RMW executed by the TMA engine (async proxy; bypasses L1tex).
__device__ __forceinline__ void bulk_reduce_add(float* gdst, uint32_t ssrc, uint32_t bytes) {
    asm volatile(
        "cp.reduce.async.bulk.global.shared::cta.bulk_group.add.f32 [%0], [%1], %2;"
        :: "l"(gdst), "r"(ssrc), "r"(bytes) : "memory");
}
#define BULK_COMMIT() asm volatile("cp.async.bulk.commit_group;" ::: "memory")
#define BULK_WAIT(n)  asm volatile("cp.async.bulk.wait_group %0;" :: "n"(n) : "memory")

// All-TMA scatter-add, properly pipelined: at steady state each thread keeps
// 3 reduce groups (3 x 256B RMWs) in flight while 2-3 stage loads stream in.
// Stage ring invariant: stage consumed at iter j is reloaded at iter j+3;
// wait_group 2 at the top of iter k guarantees groups through iter k-3 are
// drained, so the reload never clobbers live reduce sources.
__global__ __launch_bounds__(THREADS, 1) void scatter_tmared2_kernel(
    const float4* __restrict__ msg,   // [B*E, 16] float4 (batches contiguous)
    const int*    __restrict__ idx,   // [B*E]
    float*        __restrict__ out)   // [B, N, 64]
{
    extern __shared__ __align__(256) char smem[];
    const uint32_t sb  = (uint32_t)__cvta_generic_to_shared(smem);
    const uint32_t mbb = sb + SMEM_DATA;
    const int tid = threadIdx.x;

    if (tid == 0) {
#pragma unroll
        for (int s = 0; s < NSTAGES; ++s) mbar_init(mbb + s * 8, 1);
        asm volatile("fence.proxy.async.shared::cta;" ::: "memory");
    }
    __syncthreads();

    auto issue = [&](int c, int st) {
        const uint32_t full = mbb + st * 8;
        const uint32_t sp   = sb + st * STAGE_BYTES;
        mbar_expect_tx(full, STAGE_BYTES);
        bulk_g2s(sp,             msg + (long long)c * (CHUNK * 16), MSG_BYTES, full);
        bulk_g2s(sp + MSG_BYTES, idx + (long long)c * CHUNK,        IDX_BYTES, full);
    };

    // Prologue: fill PROLOGUE stages.
    if (tid == 0) {
#pragma unroll
        for (int p = 0; p < PROLOGUE; ++p) {
            const int c = blockIdx.x + p * NCTAS;
            if (c < TOTAL_CHUNKS) issue(c, p);
        }
    }

    for (int k = 0;; ++k) {
        const int c = blockIdx.x + k * NCTAS;
        if (c >= TOTAL_CHUNKS) break;
        const int st = k % NSTAGES;

        // Drain down to <=2 outstanding reduce groups per thread: the group
        // committed at iter k-3 (reading stage (k+2)%NSTAGES) is now done.
        BULK_WAIT(2);
        __syncthreads();

        // Reload stage (k+PROLOGUE)%NSTAGES with chunk c+PROLOGUE.
        if (tid == 0) {
            const int cf = blockIdx.x + (k + PROLOGUE) * NCTAS;
            if (cf < TOTAL_CHUNKS) issue(cf, (k + PROLOGUE) % NSTAGES);
        }

        // Consume stage st once its TMA load lands.
        mbar_wait(mbb + st * 8, (uint32_t)((k / NSTAGES) & 1));

        const int  b    = c / CHUNKS_PER_B;       // chunks never straddle batches
        const int* sidx = reinterpret_cast<const int*>(smem + st * STAGE_BYTES + MSG_BYTES);
        const int  node = sidx[tid];              // one edge per thread
        float* dst = out + ((long long)b * N_NODES + node) * F_FEAT;
        bulk_reduce_add(dst, sb + st * STAGE_BYTES + tid * 256, 256);
        BULK_COMMIT();
    }

    BULK_WAIT(0);   // drain all outstanding reductions before exit
}

extern "C" void kernel_launch(void* const* d_in, const int* in_sizes, int n_in,
                              void* d_out, int out_size) {
    const float4* msg = (const float4*)d_in[0];   // msg_vectors [B,E,F] f32
    const int*    idx = (const int*)d_in[1];      // start_indices [B,E] i32
    // d_in[2] = h_v, unused by the reference computation
    float* out = (float*)d_out;                   // [B,N,F] f32

    static bool attr_set = false;
    if (!attr_set) {
        cudaFuncSetAttribute(scatter_tmared2_kernel,
                             cudaFuncAttributeMaxDynamicSharedMemorySize, SMEM_BYTES);
        attr_set = true;
    }

    // 1) zero the output (harness poisons it with 0xAA)
    cudaMemsetAsync(out, 0, (size_t)out_size * sizeof(float), 0);

    // 2) all-TMA pipelined scatter-reduce (1 CTA/SM, deep reduce pipelining)
    scatter_tmared2_kernel<<<NCTAS, THREADS, SMEM_BYTES>>>(msg, idx, out);
}

// round 15
// speedup vs baseline: 1.1350x; 1.0525x over previous
#include <cuda_runtime.h>
#include <cstdint>

// Problem shape (fixed by the dataset)
#define B_BATCH 4
#define E_EDGES 320000
#define N_NODES 10000
#define F_FEAT  64

#define WARPS_PER_CTA   4
#define THREADS         (WARPS_PER_CTA * 32)            // 128
#define EDGES_PER_WARP  32
#define EDGES_PER_CTA   (WARPS_PER_CTA * EDGES_PER_WARP) // 128
#define CTAS_PER_BATCH  (E_EDGES / EDGES_PER_CTA)        // 2500 (exact)
#define BUF_PER_WARP    (EDGES_PER_WARP * 256)           // 8192 B

// 256B f32-add RMW executed by the TMA engine (async proxy; bypasses the
// SM's L1tex/RED pipeline entirely).
__device__ __forceinline__ void bulk_reduce_add(float* gdst, uint32_t ssrc) {
    asm volatile(
        "cp.reduce.async.bulk.global.shared::cta.bulk_group.add.f32 [%0], [%1], 256;"
        :: "l"(gdst), "r"(ssrc) : "memory");
}

// Warp-autonomous scatter-add via TMA bulk reductions.
// Per warp: 32 edges -> 8KB private smem buffer via coalesced LDG.128 + STS
// (the proven R8 load front-end), then one 256B cp.reduce per lane.
// No mbarriers, no CTA-wide syncs, no stage recycling: concurrency comes
// purely from 28 resident warps/SM each holding 32 async reduces in flight.
__global__ __launch_bounds__(THREADS) void scatter_warptma_kernel(
    const float4* __restrict__ msg,   // [B*E, 16] float4 (batches contiguous)
    const int*    __restrict__ idx,   // [B*E]
    float*        __restrict__ out)   // [B, N, 64]
{
    __shared__ __align__(128) char sdata[WARPS_PER_CTA * BUF_PER_WARP];

    const int b    = blockIdx.y;
    const int warp = threadIdx.x >> 5;
    const int lane = threadIdx.x & 31;

    // This warp's 32-edge window within batch b.
    const int e0 = (blockIdx.x * WARPS_PER_CTA + warp) * EDGES_PER_WARP;
    const long long gbase = (long long)b * E_EDGES + e0;

    char* buf = sdata + warp * BUF_PER_WARP;
    const uint32_t sbuf = (uint32_t)__cvta_generic_to_shared(buf);

    // ---- Load 32 edges (8KB): 16 rounds, 2 edges per round.
    // Lanes 0-15 take even edge (f4 = lane), lanes 16-31 the odd edge:
    // every LDG.128 covers two contiguous 256B segments (fully coalesced),
    // every STS round writes 512B contiguous (conflict-free).
    const int f4   = lane & 15;
    const int par  = lane >> 4;            // 0/1: even/odd edge of the round
#pragma unroll
    for (int j = 0; j < 16; ++j) {
        const int e = 2 * j + par;         // window-local edge 0..31
        const float4 v = __ldcs(msg + (gbase + e) * 16 + f4);
        *reinterpret_cast<float4*>(buf + e * 256 + f4 * 16) = v;
    }

    __syncwarp();
    // Make the generic-proxy STS visible to the async proxy.
    asm volatile("fence.proxy.async.shared::cta;" ::: "memory");

    // ---- One 256B reduction per lane (edge = lane).
    const int node = __ldg(idx + gbase + lane);
    float* dst = out + ((long long)b * N_NODES + node) * F_FEAT;
    bulk_reduce_add(dst, sbuf + lane * 256);

    asm volatile("cp.async.bulk.commit_group;" ::: "memory");
    asm volatile("cp.async.bulk.wait_group 0;" ::: "memory");
}

extern "C" void kernel_launch(void* const* d_in, const int* in_sizes, int n_in,
                              void* d_out, int out_size) {
    const float4* msg = (const float4*)d_in[0];   // msg_vectors [B,E,F] f32
    const int*    idx = (const int*)d_in[1];      // start_indices [B,E] i32
    // d_in[2] = h_v, unused by the reference computation
    float* out = (float*)d_out;                   // [B,N,F] f32

    // 1) zero the output (harness poisons it with 0xAA)
    cudaMemsetAsync(out, 0, (size_t)out_size * sizeof(float), 0);

    // 2) warp-autonomous TMA scatter-reduce
    dim3 grid(CTAS_PER_BATCH, B_BATCH);           // (2500, 4)
    scatter_warptma_kernel<<<grid, THREADS>>>(msg, idx, out);
}